// round 8
// baseline (speedup 1.0000x reference)
#include <cuda_runtime.h>

// EmbeddingToIndex: out[t] = argmin_n ||X[t] - W[n]||^2
//                         = argmin_n ( 0.5*||W[n]||^2 - X[t]·W[n] )
// X [16384, 64] fp32 (tokens flattened), W [8192, 64] fp32.
// OUTPUT WRITTEN AS FLOAT32: rel_err was exactly 1.0 with integer stores
// (ints-as-f32 = denormals ~ 0) => checker reads d_out as float32.

#define NTOK   16384
#define NCODE  8192
#define EMB    64

// Scratch (device global — allocation-free rule): 0.5 * ||W[n]||^2
__device__ float g_hb[NCODE];

__global__ void wnorm_kernel(const float* __restrict__ W) {
    int n = blockIdx.x * blockDim.x + threadIdx.x;
    if (n >= NCODE) return;
    float s = 0.0f;
#pragma unroll
    for (int k = 0; k < EMB; k++) {
        float v = W[n * EMB + k];
        s = fmaf(v, v, s);
    }
    g_hb[n] = 0.5f * s;
}

__global__ __launch_bounds__(128) void argmin_kernel(
    const float* __restrict__ X,
    const float* __restrict__ W,
    float* __restrict__ out)
{
    int t = blockIdx.x * blockDim.x + threadIdx.x;   // token id
    if (t >= NTOK) return;

    // Cache this token's 64-float row in registers.
    // Offset t*EMB floats = t*256 bytes -> float4-safe on cudaMalloc'd buffer.
    float4 x[EMB / 4];
    const float4* Xg = reinterpret_cast<const float4*>(X) + t * (EMB / 4);
#pragma unroll
    for (int q = 0; q < EMB / 4; q++) x[q] = Xg[q];

    float best = 3.4e38f;
    int   bi   = 0;

    const float4* Wg = reinterpret_cast<const float4*>(W);
    for (int n = 0; n < NCODE; n++) {
        // 4 independent accumulator chains (ILP >= lat/rt for FFMA).
        float a0 = 0.f, a1 = 0.f, a2 = 0.f, a3 = 0.f;
        const float4* w = Wg + n * (EMB / 4);
#pragma unroll
        for (int q = 0; q < EMB / 4; q += 4) {
            float4 w0 = w[q + 0], w1 = w[q + 1], w2 = w[q + 2], w3 = w[q + 3];
            a0 = fmaf(x[q + 0].x, w0.x, a0); a0 = fmaf(x[q + 0].y, w0.y, a0);
            a0 = fmaf(x[q + 0].z, w0.z, a0); a0 = fmaf(x[q + 0].w, w0.w, a0);
            a1 = fmaf(x[q + 1].x, w1.x, a1); a1 = fmaf(x[q + 1].y, w1.y, a1);
            a1 = fmaf(x[q + 1].z, w1.z, a1); a1 = fmaf(x[q + 1].w, w1.w, a1);
            a2 = fmaf(x[q + 2].x, w2.x, a2); a2 = fmaf(x[q + 2].y, w2.y, a2);
            a2 = fmaf(x[q + 2].z, w2.z, a2); a2 = fmaf(x[q + 2].w, w2.w, a2);
            a3 = fmaf(x[q + 3].x, w3.x, a3); a3 = fmaf(x[q + 3].y, w3.y, a3);
            a3 = fmaf(x[q + 3].z, w3.z, a3); a3 = fmaf(x[q + 3].w, w3.w, a3);
        }
        float dot = (a0 + a1) + (a2 + a3);
        float s = g_hb[n] - dot;        // 0.5||w||^2 - x.w  (same argmin as dist)
        if (s < best) { best = s; bi = n; }   // strict '<' => first occurrence
    }
    out[t] = (float)bi;                 // FLOAT output (indices exact in fp32)
}

extern "C" void kernel_launch(void* const* d_in, const int* in_sizes, int n_in,
                              void* d_out, int out_size) {
    const float* X = (const float*)d_in[0];   // [8,2048,64] fp32 (larger input)
    const float* W = (const float*)d_in[1];   // [8192,64]   fp32 (smaller input)
    // Unit-agnostic order guard: X is strictly larger than W whether
    // in_sizes is element counts or bytes.
    if (n_in >= 2 && in_sizes[0] < in_sizes[1]) {
        const float* tmp = X; X = W; W = tmp;
    }
    float* out = (float*)d_out;               // [16384] float32

    wnorm_kernel<<<NCODE / 128, 128>>>(W);
    argmin_kernel<<<NTOK / 128, 128>>>(X, W, out);
}

// round 13
// speedup vs baseline: 9.0966x; 9.0966x over previous
#include <cuda_runtime.h>

// EmbeddingToIndex: out[t] = argmin_n ||X[t] - W[n]||^2
//                         = argmin_n ( 0.5*||W[n]||^2 - X[t]·W[n] )
// X [16384, 64] fp32, W [8192, 64] fp32, out [16384] float32 (indices as f32).

#define NTOK   16384
#define NCODE  8192
#define EMB    64
#define TM     64     // tokens per CTA
#define TN     128    // codes per n-iteration

// Scratch (device global — allocation-free rule): 0.5 * ||W[n]||^2
__device__ float g_hb[NCODE];

__global__ void wnorm_kernel(const float* __restrict__ W) {
    int n = blockIdx.x * blockDim.x + threadIdx.x;
    if (n >= NCODE) return;
    float s = 0.0f;
#pragma unroll
    for (int k = 0; k < EMB; k++) {
        float v = W[n * EMB + k];
        s = fmaf(v, v, s);
    }
    g_hb[n] = 0.5f * s;
}

// 256 threads = 16(tx) x 16(ty). Thread tile: 4 tokens (ty) x 8 codes (tx).
// Smem float4 tiles, chunk-XOR swizzle: phys_chunk = k4 ^ ((row>>2) & 15)
// (4-bit mask — REQUIRED for 128-row tiles; without it the index overflows).
__global__ __launch_bounds__(256, 2) void argmin_gemm_kernel(
    const float* __restrict__ X,
    const float* __restrict__ W,
    float* __restrict__ out)
{
    __shared__ float4 As4[TM * 16];   // 16 KB
    __shared__ float4 Bs4[TN * 16];   // 32 KB

    const int t  = threadIdx.x;
    const int tx = t & 15;
    const int ty = t >> 4;
    const int tokenBase = blockIdx.x * TM;

    // ---- Load A tile (64 tokens x 64 k) once ----
    {
        const float4* Xg = reinterpret_cast<const float4*>(X) + tokenBase * (EMB / 4);
#pragma unroll
        for (int it = 0; it < (TM * 16) / 256; it++) {   // 4 iters
            int q   = it * 256 + t;
            int row = q >> 4;
            int k4  = q & 15;
            As4[row * 16 + (k4 ^ ((row >> 2) & 15))] = Xg[q];
        }
    }

    float best[4];
    int   bidx[4];
#pragma unroll
    for (int i = 0; i < 4; i++) { best[i] = 3.4e38f; bidx[i] = 0; }

    const float4* Wg = reinterpret_cast<const float4*>(W);

    for (int nb = 0; nb < NCODE; nb += TN) {
        __syncthreads();  // prior-iter Bs reads done (also covers As on iter 0)
#pragma unroll
        for (int it = 0; it < (TN * 16) / 256; it++) {   // 8 iters
            int q   = it * 256 + t;
            int row = q >> 4;                            // 0..127
            int k4  = q & 15;
            Bs4[row * 16 + (k4 ^ ((row >> 2) & 15))] = Wg[nb * (EMB / 4) + q];
        }
        __syncthreads();

        float acc[4][8];
#pragma unroll
        for (int i = 0; i < 4; i++)
#pragma unroll
            for (int j = 0; j < 8; j++) acc[i][j] = 0.f;

#pragma unroll
        for (int k4 = 0; k4 < 16; k4++) {
            float4 a[4], b[8];
            // a row = ty*4+i  -> (row>>2)&15 == ty
#pragma unroll
            for (int i = 0; i < 4; i++)
                a[i] = As4[(ty * 4 + i) * 16 + (k4 ^ ty)];
            // b row = tx*8+j  -> (row>>2)&15 == (tx*2 + (j>>2)) & 15
#pragma unroll
            for (int j = 0; j < 8; j++)
                b[j] = Bs4[(tx * 8 + j) * 16 + (k4 ^ ((tx * 2 + (j >> 2)) & 15))];
#pragma unroll
            for (int i = 0; i < 4; i++)
#pragma unroll
                for (int j = 0; j < 8; j++) {
                    acc[i][j] = fmaf(a[i].x, b[j].x, acc[i][j]);
                    acc[i][j] = fmaf(a[i].y, b[j].y, acc[i][j]);
                    acc[i][j] = fmaf(a[i].z, b[j].z, acc[i][j]);
                    acc[i][j] = fmaf(a[i].w, b[j].w, acc[i][j]);
                }
        }

        // score = 0.5||w||^2 - dot ; strict '<', ascending j => first occurrence
#pragma unroll
        for (int j = 0; j < 8; j++) {
            const int   code = nb + tx * 8 + j;
            const float hb   = g_hb[code];
#pragma unroll
            for (int i = 0; i < 4; i++) {
                float s = hb - acc[i][j];
                if (s < best[i]) { best[i] = s; bidx[i] = code; }
            }
        }
    }

    // ---- Argmin reduce across tx (xor masks 1..8 stay within tx bits) ----
#pragma unroll
    for (int off = 8; off >= 1; off >>= 1) {
#pragma unroll
        for (int i = 0; i < 4; i++) {
            float os = __shfl_xor_sync(0xffffffffu, best[i], off);
            int   oi = __shfl_xor_sync(0xffffffffu, bidx[i], off);
            if (os < best[i] || (os == best[i] && oi < bidx[i])) {
                best[i] = os; bidx[i] = oi;
            }
        }
    }
    if (tx == 0) {
#pragma unroll
        for (int i = 0; i < 4; i++)
            out[tokenBase + ty * 4 + i] = (float)bidx[i];
    }
}

extern "C" void kernel_launch(void* const* d_in, const int* in_sizes, int n_in,
                              void* d_out, int out_size) {
    const float* X = (const float*)d_in[0];   // larger input = X
    const float* W = (const float*)d_in[1];   // smaller input = W
    if (n_in >= 2 && in_sizes[0] < in_sizes[1]) {
        const float* tmp = X; X = W; W = tmp;
    }
    float* out = (float*)d_out;               // [16384] float32

    wnorm_kernel<<<NCODE / 128, 128>>>(W);
    argmin_gemm_kernel<<<NTOK / TM, 256>>>(X, W, out);
}

// round 16
// speedup vs baseline: 11.4223x; 1.2557x over previous
#include <cuda_runtime.h>

// EmbeddingToIndex: out[t] = argmin_n ||X[t] - W[n]||^2
//                         = argmin_n ( 0.5*||W[n]||^2 - X[t]·W[n] )
// X [16384,64] fp32, W [8192,64] fp32, out [16384] float32 (indices as f32).
// Inner product via packed fp32 FMA (fma.rn.f32x2): 2 codes per instruction,
// bit-identical per-code k-ascending fp32 chains (matches the passing R13 kernel).

#define NTOK   16384
#define NCODE  8192
#define EMB    64
#define TM     64     // tokens per CTA
#define TN     128    // codes per n-iteration

__device__ float g_hb[NCODE];   // 0.5 * ||W[n]||^2

__global__ void wnorm_kernel(const float* __restrict__ W) {
    int n = blockIdx.x * blockDim.x + threadIdx.x;
    if (n >= NCODE) return;
    float s = 0.0f;
#pragma unroll
    for (int k = 0; k < EMB; k++) {
        float v = W[n * EMB + k];
        s = fmaf(v, v, s);
    }
    g_hb[n] = 0.5f * s;
}

__device__ __forceinline__ void fma2(unsigned long long& d,
                                     unsigned long long a,
                                     unsigned long long b) {
    asm("fma.rn.f32x2 %0, %1, %2, %3;" : "=l"(d) : "l"(a), "l"(b), "l"(d));
}
__device__ __forceinline__ unsigned long long pack2(float v) {
    unsigned long long r;
    unsigned int u = __float_as_uint(v);
    asm("mov.b64 %0, {%1, %1};" : "=l"(r) : "r"(u));
    return r;
}

// 256 threads = 16(tx) x 16(ty). Thread tile: 4 tokens (ty) x 8 codes (tx).
// A smem: float4 [token][k4-chunk], XOR swizzle (broadcast reads).
// B smem: TRANSPOSED [k][code], stored as u64 code-pairs:
//   BsU[k*64 + pair], pair = code/2. Lane tx reads pair 16*p + tx
//   -> banks {2tx, 2tx+1}: exact 32-bank cover per 16 lanes, other half
//   broadcasts => conflict-free LDS.64.
__global__ __launch_bounds__(256, 2) void argmin_gemm_kernel(
    const float* __restrict__ X,
    const float* __restrict__ W,
    float* __restrict__ out)
{
    __shared__ float4 As4[TM * 16];                 // 16 KB
    __shared__ unsigned long long BsU[EMB * (TN/2)]; // 64 k x 64 pairs = 32 KB
    float* BsF = reinterpret_cast<float*>(BsU);

    const int t  = threadIdx.x;
    const int tx = t & 15;
    const int ty = t >> 4;
    const int tokenBase = blockIdx.x * TM;

    // ---- A tile (64 tokens x 64 k), once ----
    {
        const float4* Xg = reinterpret_cast<const float4*>(X) + tokenBase * (EMB / 4);
#pragma unroll
        for (int it = 0; it < (TM * 16) / 256; it++) {   // 4 iters
            int q   = it * 256 + t;
            int row = q >> 4;
            int k4  = q & 15;
            As4[row * 16 + (k4 ^ ((row >> 2) & 15))] = Xg[q];
        }
    }

    float best[4];
    int   bidx[4];
#pragma unroll
    for (int i = 0; i < 4; i++) { best[i] = 3.4e38f; bidx[i] = 0; }

    const float4* Wg = reinterpret_cast<const float4*>(W);

    for (int nb = 0; nb < NCODE; nb += TN) {
        __syncthreads();  // prior-iter Bs reads done (covers As on iter 0)
        // ---- B tile fill, transposed: BsF[k*128 + code] = W[nb+code][k] ----
        // q: code = q&127 (consecutive per warp -> conflict-free STS),
        //    k4 = q>>7. Global reads are 16B scattered; W is L2-resident.
#pragma unroll
        for (int it = 0; it < (TN * 16) / 256; it++) {   // 8 iters
            int q    = it * 256 + t;
            int code = q & 127;
            int k4   = q >> 7;
            float4 v = Wg[(nb + code) * (EMB / 4) + k4];
            BsF[(4 * k4 + 0) * TN + code] = v.x;
            BsF[(4 * k4 + 1) * TN + code] = v.y;
            BsF[(4 * k4 + 2) * TN + code] = v.z;
            BsF[(4 * k4 + 3) * TN + code] = v.w;
        }
        __syncthreads();

        unsigned long long acc2[4][4];   // [token i][code-pair p], 2 codes each
#pragma unroll
        for (int i = 0; i < 4; i++)
#pragma unroll
            for (int p = 0; p < 4; p++) acc2[i][p] = 0ull;

#pragma unroll
        for (int k4 = 0; k4 < 16; k4++) {
            float4 a4[4];
#pragma unroll
            for (int i = 0; i < 4; i++)
                a4[i] = As4[(ty * 4 + i) * 16 + (k4 ^ ty)];   // broadcast

#pragma unroll
            for (int ks = 0; ks < 4; ks++) {
                const int k = 4 * k4 + ks;
                unsigned long long b2[4];
#pragma unroll
                for (int p = 0; p < 4; p++)
                    b2[p] = BsU[k * (TN / 2) + 16 * p + tx];  // conflict-free
                float av[4] = {
                    ks == 0 ? a4[0].x : ks == 1 ? a4[0].y : ks == 2 ? a4[0].z : a4[0].w,
                    ks == 0 ? a4[1].x : ks == 1 ? a4[1].y : ks == 2 ? a4[1].z : a4[1].w,
                    ks == 0 ? a4[2].x : ks == 1 ? a4[2].y : ks == 2 ? a4[2].z : a4[2].w,
                    ks == 0 ? a4[3].x : ks == 1 ? a4[3].y : ks == 2 ? a4[3].z : a4[3].w };
#pragma unroll
                for (int i = 0; i < 4; i++) {
                    unsigned long long a2 = pack2(av[i]);
#pragma unroll
                    for (int p = 0; p < 4; p++)
                        fma2(acc2[i][p], a2, b2[p]);
                }
            }
        }

        // ---- scores: s = 0.5||w||^2 - dot ; lo code before hi, p ascending ----
#pragma unroll
        for (int p = 0; p < 4; p++) {
            const int codeLo = nb + 32 * p + 2 * tx;
            const float hbLo = g_hb[codeLo];
            const float hbHi = g_hb[codeLo + 1];
#pragma unroll
            for (int i = 0; i < 4; i++) {
                unsigned int ulo, uhi;
                asm("mov.b64 {%0, %1}, %2;" : "=r"(ulo), "=r"(uhi) : "l"(acc2[i][p]));
                float sLo = hbLo - __uint_as_float(ulo);
                float sHi = hbHi - __uint_as_float(uhi);
                if (sLo < best[i]) { best[i] = sLo; bidx[i] = codeLo; }
                if (sHi < best[i]) { best[i] = sHi; bidx[i] = codeLo + 1; }
            }
        }
    }

    // ---- Argmin reduce across tx (16 lanes; index tie-break => first occurrence) ----
#pragma unroll
    for (int off = 8; off >= 1; off >>= 1) {
#pragma unroll
        for (int i = 0; i < 4; i++) {
            float os = __shfl_xor_sync(0xffffffffu, best[i], off);
            int   oi = __shfl_xor_sync(0xffffffffu, bidx[i], off);
            if (os < best[i] || (os == best[i] && oi < bidx[i])) {
                best[i] = os; bidx[i] = oi;
            }
        }
    }
    if (tx == 0) {
#pragma unroll
        for (int i = 0; i < 4; i++)
            out[tokenBase + ty * 4 + i] = (float)bidx[i];
    }
}

extern "C" void kernel_launch(void* const* d_in, const int* in_sizes, int n_in,
                              void* d_out, int out_size) {
    const float* X = (const float*)d_in[0];   // larger input = X
    const float* W = (const float*)d_in[1];   // smaller input = W
    if (n_in >= 2 && in_sizes[0] < in_sizes[1]) {
        const float* tmp = X; X = W; W = tmp;
    }
    float* out = (float*)d_out;               // [16384] float32

    wnorm_kernel<<<NCODE / 128, 128>>>(W);
    argmin_gemm_kernel<<<NTOK / TM, 256>>>(X, W, out);
}